// round 7
// baseline (speedup 1.0000x reference)
#include <cuda_runtime.h>
#include <math.h>

// Problem constants
#define B 512
#define S 16
#define H 501
#define C 7
#define KP 512          // padded K (inner dim)
#define DEP_OFF 0
#define ENC_OFF (B*S*S) // 131072

typedef unsigned long long u64;

// ---------------- device state ----------------
__device__ float g_gs  [B][KP];        // graph state (padded, tail zeros)
__device__ float g_hin [B][KP];        // h_in buffer (padded, tail zeros)
__device__ float g_zpad[B][KP];        // padded z
__device__ float g_WcatT[KP][1024];    // B matrix for K1: [k][2h+e], e=0 gate, e=1 map
__device__ float g_Whh3T[KP][1536];    // B matrix for K2: [k][3h+j], j=r,z,n
__device__ float g_WlinT[KP][KP];      // W_lin1^T padded
__device__ float g_f0[KP];             // sigmoid(b_gate)*b_map
__device__ int   g_cls[B*S];           // argmax of one-hot node encoding
__device__ float g_d[B][S];            // cached dots nhs[j]·we2
__device__ float g_aprev[B];           // cached dot hv·we1

__device__ __forceinline__ float sigm(float x){ return 1.0f/(1.0f+expf(-x)); }

// packed fp32x2 FMA (Blackwell FFMA2) — d = a*b + c elementwise on 2 lanes
__device__ __forceinline__ u64 ffma2(u64 a, u64 b, u64 c){
    u64 d;
    asm("fma.rn.f32x2 %0, %1, %2, %3;" : "=l"(d) : "l"(a), "l"(b), "l"(c));
    return d;
}
__device__ __forceinline__ float lo32(u64 v){ return __uint_as_float((unsigned)v); }
__device__ __forceinline__ float hi32(u64 v){ return __uint_as_float((unsigned)(v>>32)); }

// ---------------- init: transpose/interleave weights, pad z, f0, classes ----------------
__global__ void kinit(const float* __restrict__ Wg, const float* __restrict__ Wm,
                      const float* __restrict__ Whh, const float* __restrict__ Wlin,
                      const float* __restrict__ bgate, const float* __restrict__ bmap,
                      const float* __restrict__ z, const float* __restrict__ ne)
{
    int gt = blockIdx.x*blockDim.x + threadIdx.x;
    int gstep = gridDim.x*blockDim.x;
    for (int i=gt; i<KP*1024; i+=gstep){
        int k = i>>10, n = i & 1023; int h = n>>1, e = n&1;
        float v = 0.f;
        if (k<H && h<H) v = e ? Wm[h*H+k] : Wg[h*H+k];
        (&g_WcatT[0][0])[i] = v;
    }
    for (int i=gt; i<KP*1536; i+=gstep){
        int k = i/1536, n = i%1536; int h = n/3, j = n%3;
        float v = 0.f;
        if (k<H && h<H) v = Whh[(j*H+h)*H + k];
        (&g_Whh3T[0][0])[i] = v;
    }
    for (int i=gt; i<KP*KP; i+=gstep){
        int k = i>>9, h = i & 511;
        float v = 0.f;
        if (k<H && h<H) v = Wlin[h*H+k];
        (&g_WlinT[0][0])[i] = v;
    }
    for (int i=gt; i<B*KP; i+=gstep){
        int b = i>>9, k = i & 511;
        (&g_zpad[0][0])[i] = (k<H) ? z[b*H+k] : 0.f;
    }
    for (int i=gt; i<KP; i+=gstep){
        g_f0[i] = (i<H) ? sigm(bgate[i])*bmap[i] : 0.f;
    }
    for (int i=gt; i<B*S; i+=gstep){
        const float* p = ne + i*C;
        int best = 0; float bv = p[0];
        #pragma unroll
        for (int c=1;c<C;c++){ if (p[c] > bv){ bv = p[c]; best = c; } }
        g_cls[i] = best;
    }
}

// ---------------- 64x64 GEMM core, 256 thr, BK=16, packed f32x2 ----------------
// thread tile: 4 rows (2 packed row-pairs) x 4 cols. Bsd holds duplicated (b,b) pairs.
__device__ __forceinline__ void gemm_core_f2(
    const float* __restrict__ A,      // [..][KP] rows m0..m0+63
    const float* __restrict__ Bm,     // [KP][NB]
    int NB, int m0, int n0,
    u64 acc[2][4], float As[16][68], float Bsd[16][128])
{
    int t = threadIdx.x;
    int tx = t & 15, ty = t >> 4;
    int am = t & 63, akq = t >> 6;      // A producer
    int bk = t >> 4, bn = (t & 15)*4;   // B producer

    for (int k0 = 0; k0 < KP; k0 += 16){
        float4 v = *(const float4*)&A[(size_t)(m0+am)*KP + k0 + akq*4];
        As[akq*4+0][am] = v.x;
        As[akq*4+1][am] = v.y;
        As[akq*4+2][am] = v.z;
        As[akq*4+3][am] = v.w;
        float4 w = *(const float4*)&Bm[(size_t)(k0+bk)*NB + n0 + bn];
        float4 d0 = make_float4(w.x,w.x,w.y,w.y);
        float4 d1 = make_float4(w.z,w.z,w.w,w.w);
        *(float4*)&Bsd[bk][bn*2]   = d0;
        *(float4*)&Bsd[bk][bn*2+4] = d1;
        __syncthreads();
        #pragma unroll
        for (int kk = 0; kk < 16; kk++){
            ulonglong2 a01 = *(const ulonglong2*)&As[kk][ty*4];
            ulonglong2 b01 = *(const ulonglong2*)&Bsd[kk][tx*8];
            ulonglong2 b23 = *(const ulonglong2*)&Bsd[kk][tx*8+4];
            u64 av[2] = {a01.x, a01.y};
            u64 bv[4] = {b01.x, b01.y, b23.x, b23.y};
            #pragma unroll
            for (int p=0;p<2;p++)
                #pragma unroll
                for (int j=0;j<4;j++) acc[p][j] = ffma2(av[p], bv[j], acc[p][j]);
        }
        __syncthreads();
    }
}

// ---------------- GEMM gs0 = zpad @ WlinT + b_lin1 ; writes g_gs and g_hin ----------------
// grid 64 (8 ntiles x 8 mtiles), 256 thr
__global__ __launch_bounds__(256) void kgemm0(const float* __restrict__ blin)
{
    __shared__ float As[16][68];
    __shared__ float Bsd[16][128];
    int nt = blockIdx.x & 7, mt = blockIdx.x >> 3;
    int m0 = mt*64, n0 = nt*64;
    u64 acc[2][4];
    #pragma unroll
    for (int p=0;p<2;p++)
        #pragma unroll
        for (int j=0;j<4;j++) acc[p][j] = 0ull;
    gemm_core_f2(&g_zpad[0][0], &g_WlinT[0][0], KP, m0, n0, acc, As, Bsd);
    int t = threadIdx.x, tx = t & 15, ty = t >> 4;
    #pragma unroll
    for (int p=0;p<2;p++){
        #pragma unroll
        for (int half=0;half<2;half++){
            int m = m0 + ty*4 + p*2 + half;
            #pragma unroll
            for (int j=0;j<4;j++){
                int h = n0 + tx*4 + j;
                float a = half ? hi32(acc[p][j]) : lo32(acc[p][j]);
                float v = (h<H) ? a + blin[h] : 0.f;
                g_gs[m][h] = v;
                g_hin[m][h] = v;
            }
        }
    }
}

// ---------------- fused: [gemm1(idx) | vert(idx) | edge(idx-1)] -----------------
// all parts read the SAME g_gs snapshot; gemm writes g_hin, vert/edge write out + caches
__global__ __launch_bounds__(256) void kfused1(
    const float* __restrict__ dep, const float* __restrict__ bgate,
    const float* __restrict__ bmap, const float* __restrict__ Wv,
    const float* __restrict__ bv, const float* __restrict__ We,
    const float* __restrict__ be, float* __restrict__ out, int idx)
{
    __shared__ float As[16][68];
    __shared__ float Bsd[16][128];
    int gemmBlocks = (idx >= 1) ? 128 : 0;
    int bid = blockIdx.x;
    int t = threadIdx.x;

    if (bid < gemmBlocks){
        // ---- GEMM1: GM = gs @ WcatT, epilogue -> g_hin ----
        int nt = bid & 15, mt = bid >> 4;
        int m0 = mt*64, n0 = nt*64;
        u64 acc[2][4];
        #pragma unroll
        for (int p=0;p<2;p++)
            #pragma unroll
            for (int j=0;j<4;j++) acc[p][j] = 0ull;
        gemm_core_f2(&g_gs[0][0], &g_WcatT[0][0], 1024, m0, n0, acc, As, Bsd);
        int tx = t & 15, ty = t >> 4;
        // cols n = n0 + tx*4 + j  ->  h = n>>1, e = n&1; j pairs (0,1)->h0, (2,3)->h1
        #pragma unroll
        for (int p=0;p<2;p++){
            #pragma unroll
            for (int half=0;half<2;half++){
                int m = m0 + ty*4 + p*2 + half;
                float rb = dep[m*(S*S) + idx*S + (idx-1)];
                #pragma unroll
                for (int q=0;q<2;q++){           // which h within the 4 cols
                    int h = (n0>>1) + tx*2 + q;
                    float G = half ? hi32(acc[p][2*q])   : lo32(acc[p][2*q]);
                    float M = half ? hi32(acc[p][2*q+1]) : lo32(acc[p][2*q+1]);
                    float val = 0.f;
                    if (h < H){
                        float f0 = g_f0[h];
                        float fv = (rb != 0.f) ? sigm(G + bgate[h]) * (M + bmap[h]) : f0;
                        val = 15.f*f0 + fv;
                    }
                    g_hin[m][h] = val;
                }
            }
        }
        return;
    }

    float* red = &As[0][0];
    int r = bid - gemmBlocks;
    if (r < 512){
        // ---- vertex logits + softmax for idx, b = r ----
        int b = r;
        int w = t >> 5, lane = t & 31;
        float sA = 0.f;
        if (w < C){
            for (int k = lane; k < H; k += 32) sA += g_gs[b][k] * Wv[w*H + k];
            #pragma unroll
            for (int o=16;o>0;o>>=1) sA += __shfl_down_sync(0xffffffffu, sA, o);
            if (lane == 0) red[w] = sA + bv[w];
        }
        __syncthreads();
        if (t == 0){
            float mx = red[0];
            #pragma unroll
            for (int c=1;c<C;c++) mx = fmaxf(mx, red[c]);
            float e[C]; float sum = 0.f;
            #pragma unroll
            for (int c=0;c<C;c++){ e[c] = expf(red[c]-mx); sum += e[c]; }
            float inv = 1.f/sum;
            float* o = out + ENC_OFF + (b*S + idx)*C;
            #pragma unroll
            for (int c=0;c<C;c++) o[c] = e[c]*inv;
        }
    } else {
        // ---- edge row for eidx = idx-1, b = r-512 (only launched when idx>=1) ----
        int b = r - 512;
        int eidx = idx - 1;
        int w = t >> 5, lane = t & 31;
        float s1 = 0.f, s2 = 0.f;
        for (int k = t; k < H; k += 256){
            float g = g_gs[b][k];
            s1 += g * We[k];
            s2 += g * We[H + k];
        }
        #pragma unroll
        for (int o=16;o>0;o>>=1){
            s1 += __shfl_down_sync(0xffffffffu, s1, o);
            s2 += __shfl_down_sync(0xffffffffu, s2, o);
        }
        if (lane == 0){ red[w] = s1; red[8+w] = s2; }
        __syncthreads();
        if (t == 0){
            float a_new = 0.f, d_new = 0.f;
            #pragma unroll
            for (int i=0;i<8;i++){ a_new += red[i]; d_new += red[8+i]; }
            float bev = be[0];
            float a_old = g_aprev[b];
            float* row = out + DEP_OFF + (b*S + eidx)*S;
            #pragma unroll
            for (int col=0; col<S; col++){
                float v;
                if (col >= eidx) v = 0.f;
                else if (col == eidx-1) v = (a_old + g_d[b][eidx-1] + bev >= 0.f) ? 1.f : 0.f;
                else v = (a_new + g_d[b][col] + bev >= 0.f) ? 1.f : 0.f;
                row[col] = v;
            }
            g_d[b][eidx] = d_new;
            g_aprev[b] = a_new;
        }
    }
}

// ---------------- K2: gh = h_in @ Whh3T, GRU epilogue -> g_gs ----------------
// grid 256 (32 ntiles x 8 mtiles), 256 thr, BM=64 BN=48 BK=16, tile 4 rows x 3 cols (f32x2)
__global__ __launch_bounds__(256) void kgemm2(const float* __restrict__ Wih,
                                              const float* __restrict__ bih,
                                              const float* __restrict__ bhh, int idx)
{
    __shared__ float As[16][68];
    __shared__ float Bsd[16][96];
    int bid = blockIdx.x;
    int nt = bid & 31, mt = bid >> 5;
    int m0 = mt*64, n0 = nt*48;
    int t = threadIdx.x, tx = t & 15, ty = t >> 4;
    int am = t & 63, akq = t >> 6;
    u64 acc[2][3];
    #pragma unroll
    for (int p=0;p<2;p++)
        #pragma unroll
        for (int j=0;j<3;j++) acc[p][j] = 0ull;

    for (int k0 = 0; k0 < KP; k0 += 16){
        float4 v = *(const float4*)&g_hin[m0+am][k0 + akq*4];
        As[akq*4+0][am] = v.x;
        As[akq*4+1][am] = v.y;
        As[akq*4+2][am] = v.z;
        As[akq*4+3][am] = v.w;
        if (t < 192){
            int kb = t/12, nb = (t%12)*4;
            float4 w = *(const float4*)&g_Whh3T[k0+kb][n0 + nb];
            float4 d0 = make_float4(w.x,w.x,w.y,w.y);
            float4 d1 = make_float4(w.z,w.z,w.w,w.w);
            *(float4*)&Bsd[kb][nb*2]   = d0;
            *(float4*)&Bsd[kb][nb*2+4] = d1;
        }
        __syncthreads();
        #pragma unroll
        for (int kk = 0; kk < 16; kk++){
            ulonglong2 a01 = *(const ulonglong2*)&As[kk][ty*4];
            u64 av[2] = {a01.x, a01.y};
            u64 b0 = *(const u64*)&Bsd[kk][tx*6];
            u64 b1 = *(const u64*)&Bsd[kk][tx*6+2];
            u64 b2 = *(const u64*)&Bsd[kk][tx*6+4];
            #pragma unroll
            for (int p=0;p<2;p++){
                acc[p][0] = ffma2(av[p], b0, acc[p][0]);
                acc[p][1] = ffma2(av[p], b1, acc[p][1]);
                acc[p][2] = ffma2(av[p], b2, acc[p][2]);
            }
        }
        __syncthreads();
    }
    int h = nt*16 + tx;
    if (h < H){
        float bh_r = bhh[h], bh_z = bhh[H+h], bh_n = bhh[2*H+h];
        float bi_r = bih[h], bi_z = bih[H+h], bi_n = bih[2*H+h];
        #pragma unroll
        for (int p=0;p<2;p++){
            #pragma unroll
            for (int half=0;half<2;half++){
                int m = m0 + ty*4 + p*2 + half;
                int c = g_cls[m*S + idx];
                float gh_r = (half ? hi32(acc[p][0]) : lo32(acc[p][0])) + bh_r;
                float gh_z = (half ? hi32(acc[p][1]) : lo32(acc[p][1])) + bh_z;
                float gh_n = (half ? hi32(acc[p][2]) : lo32(acc[p][2])) + bh_n;
                float gi_r = Wih[(      h)*C + c] + bi_r;
                float gi_z = Wih[(H   + h)*C + c] + bi_z;
                float gi_n = Wih[(2*H + h)*C + c] + bi_n;
                float rr = sigm(gi_r + gh_r);
                float u  = sigm(gi_z + gh_z);
                float nn = tanhf(gi_n + rr*gh_n);
                float hv = (1.f-u)*nn + u*g_hin[m][h];
                g_gs[m][h] = hv;
            }
        }
    }
}

// ---------------- final edge row (idx = S-1) ----------------
__global__ __launch_bounds__(256) void kedge_final(const float* __restrict__ We,
                                                   const float* __restrict__ be,
                                                   float* __restrict__ out)
{
    __shared__ float red[16];
    int b = blockIdx.x;
    int t = threadIdx.x;
    int w = t >> 5, lane = t & 31;
    const int eidx = S - 1;
    float s1 = 0.f;
    for (int k = t; k < H; k += 256){
        s1 += g_gs[b][k] * We[k];
    }
    #pragma unroll
    for (int o=16;o>0;o>>=1) s1 += __shfl_down_sync(0xffffffffu, s1, o);
    if (lane == 0) red[w] = s1;
    __syncthreads();
    if (t == 0){
        float a_new = 0.f;
        #pragma unroll
        for (int i=0;i<8;i++) a_new += red[i];
        float bev = be[0];
        float a_old = g_aprev[b];
        float* row = out + DEP_OFF + (b*S + eidx)*S;
        #pragma unroll
        for (int col=0; col<S; col++){
            float v;
            if (col >= eidx) v = 0.f;
            else if (col == eidx-1) v = (a_old + g_d[b][eidx-1] + bev >= 0.f) ? 1.f : 0.f;
            else v = (a_new + g_d[b][col] + bev >= 0.f) ? 1.f : 0.f;
            row[col] = v;
        }
    }
}

// ---------------- launch ----------------
extern "C" void kernel_launch(void* const* d_in, const int* in_sizes, int n_in,
                              void* d_out, int out_size)
{
    const float* z     = (const float*)d_in[0];
    const float* dep   = (const float*)d_in[1];
    const float* ne    = (const float*)d_in[2];
    const float* Wlin  = (const float*)d_in[3];
    const float* blin  = (const float*)d_in[4];
    const float* Wv    = (const float*)d_in[5];
    const float* bv    = (const float*)d_in[6];
    const float* We    = (const float*)d_in[7];
    const float* be    = (const float*)d_in[8];
    const float* Wg    = (const float*)d_in[9];
    const float* bgate = (const float*)d_in[10];
    const float* Wm    = (const float*)d_in[11];
    const float* bmap  = (const float*)d_in[12];
    const float* Wih   = (const float*)d_in[13];
    const float* bih   = (const float*)d_in[14];
    const float* Whh   = (const float*)d_in[15];
    const float* bhh   = (const float*)d_in[16];
    float* out = (float*)d_out;

    kinit<<<1024, 256>>>(Wg, Wm, Whh, Wlin, bgate, bmap, z, ne);
    kgemm0<<<64, 256>>>(blin);
    for (int idx=0; idx<S; ++idx){
        int grid = (idx >= 1) ? (128 + 512 + 512) : 512;
        kfused1<<<grid, 256>>>(dep, bgate, bmap, Wv, bv, We, be, out, idx);
        kgemm2<<<256, 256>>>(Wih, bih, bhh, idx);
    }
    kedge_final<<<B, 256>>>(We, be, out);
    (void)in_sizes; (void)n_in; (void)out_size;
}

// round 10
// speedup vs baseline: 1.7680x; 1.7680x over previous
#include <cuda_runtime.h>
#include <math.h>

// Problem constants
#define B 512
#define S 16
#define H 501
#define C 7
#define KP 512          // padded K (inner dim)
#define DEP_OFF 0
#define ENC_OFF (B*S*S) // 131072

// ---------------- device state ----------------
__device__ float g_gs  [B][KP];        // graph state (padded, tail zeros)
__device__ float g_hin [B][KP];        // h_in buffer (padded, tail zeros)
__device__ float g_zpad[B][KP];        // padded z
__device__ float g_WcatT[KP][1024];    // B matrix for K1: [k][2h+e], e=0 gate, e=1 map
__device__ float g_Whh3T[KP][1536];    // B matrix for K2: [k][3h+j], j=r,z,n
__device__ float g_WlinT[KP][KP];      // W_lin1^T padded
__device__ float g_f0[KP];             // sigmoid(b_gate)*b_map
__device__ int   g_cls[B*S];           // argmax of one-hot node encoding
__device__ float g_d[B][S];            // cached dots nhs[j]·we2
__device__ float g_aprev[B];           // cached dot hv·we1

__device__ __forceinline__ float sigm(float x){ return 1.0f/(1.0f+expf(-x)); }

// ---------------- init: transpose/interleave weights, pad z, f0, classes ----------------
__global__ void kinit(const float* __restrict__ Wg, const float* __restrict__ Wm,
                      const float* __restrict__ Whh, const float* __restrict__ Wlin,
                      const float* __restrict__ bgate, const float* __restrict__ bmap,
                      const float* __restrict__ z, const float* __restrict__ ne)
{
    int gt = blockIdx.x*blockDim.x + threadIdx.x;
    int gstep = gridDim.x*blockDim.x;
    for (int i=gt; i<KP*1024; i+=gstep){
        int k = i>>10, n = i & 1023; int h = n>>1, e = n&1;
        float v = 0.f;
        if (k<H && h<H) v = e ? Wm[h*H+k] : Wg[h*H+k];
        (&g_WcatT[0][0])[i] = v;
    }
    for (int i=gt; i<KP*1536; i+=gstep){
        int k = i/1536, n = i%1536; int h = n/3, j = n%3;
        float v = 0.f;
        if (k<H && h<H) v = Whh[(j*H+h)*H + k];
        (&g_Whh3T[0][0])[i] = v;
    }
    for (int i=gt; i<KP*KP; i+=gstep){
        int k = i>>9, h = i & 511;
        float v = 0.f;
        if (k<H && h<H) v = Wlin[h*H+k];
        (&g_WlinT[0][0])[i] = v;
    }
    for (int i=gt; i<B*KP; i+=gstep){
        int b = i>>9, k = i & 511;
        (&g_zpad[0][0])[i] = (k<H) ? z[b*H+k] : 0.f;
    }
    for (int i=gt; i<KP; i+=gstep){
        g_f0[i] = (i<H) ? sigm(bgate[i])*bmap[i] : 0.f;
    }
    for (int i=gt; i<B*S; i+=gstep){
        const float* p = ne + i*C;
        int best = 0; float bv = p[0];
        #pragma unroll
        for (int c=1;c<C;c++){ if (p[c] > bv){ bv = p[c]; best = c; } }
        g_cls[i] = best;
    }
}

// ---------------- double-buffered 64x64 GEMM core: BM=64, BN=64, BK=16, 256 thr, tile 4x4
__device__ __forceinline__ void gemm_db_64x64(
    const float* __restrict__ A,      // [..][KP] rows m0..m0+63
    const float* __restrict__ Bm,     // [KP][NB]
    int NB, int m0, int n0,
    float acc[4][4], float As[2][16][68], float Bs[2][16][64])
{
    int t = threadIdx.x;
    int tx = t & 15, ty = t >> 4;
    int am = t & 63, akq = t >> 6;      // A producer: row, 4-float chunk
    int bk = t >> 4, bn = (t & 15)*4;   // B producer

    // prologue: slice 0
    float4 av = *(const float4*)&A[(size_t)(m0+am)*KP + akq*4];
    float4 bv = *(const float4*)&Bm[(size_t)bk*NB + n0 + bn];
    As[0][akq*4+0][am]=av.x; As[0][akq*4+1][am]=av.y;
    As[0][akq*4+2][am]=av.z; As[0][akq*4+3][am]=av.w;
    *(float4*)&Bs[0][bk][bn] = bv;
    __syncthreads();

    int buf = 0;
    for (int k0 = 16; k0 <= KP; k0 += 16){
        bool more = (k0 < KP);
        if (more){
            av = *(const float4*)&A[(size_t)(m0+am)*KP + k0 + akq*4];
            bv = *(const float4*)&Bm[(size_t)(k0+bk)*NB + n0 + bn];
        }
        #pragma unroll
        for (int kk = 0; kk < 16; kk++){
            float4 a4 = *(const float4*)&As[buf][kk][ty*4];
            float4 b4 = *(const float4*)&Bs[buf][kk][tx*4];
            float a[4] = {a4.x,a4.y,a4.z,a4.w};
            float bb[4] = {b4.x,b4.y,b4.z,b4.w};
            #pragma unroll
            for (int i=0;i<4;i++)
                #pragma unroll
                for (int j=0;j<4;j++) acc[i][j] += a[i]*bb[j];
        }
        if (more){
            int nb = buf ^ 1;
            As[nb][akq*4+0][am]=av.x; As[nb][akq*4+1][am]=av.y;
            As[nb][akq*4+2][am]=av.z; As[nb][akq*4+3][am]=av.w;
            *(float4*)&Bs[nb][bk][bn] = bv;
            __syncthreads();
            buf = nb;
        }
    }
}

// ---------------- GEMM gs0 = zpad @ WlinT + b_lin1 ; writes g_gs and g_hin ----------------
// grid 64 (8 ntiles x 8 mtiles), 256 thr
__global__ __launch_bounds__(256) void kgemm0(const float* __restrict__ blin)
{
    __shared__ float As[2][16][68];
    __shared__ float Bs[2][16][64];
    int nt = blockIdx.x & 7, mt = blockIdx.x >> 3;
    int m0 = mt*64, n0 = nt*64;
    float acc[4][4];
    #pragma unroll
    for (int i=0;i<4;i++)
        #pragma unroll
        for (int j=0;j<4;j++) acc[i][j] = 0.f;
    gemm_db_64x64(&g_zpad[0][0], &g_WlinT[0][0], KP, m0, n0, acc, As, Bs);
    int t = threadIdx.x, tx = t & 15, ty = t >> 4;
    #pragma unroll
    for (int i=0;i<4;i++){
        int m = m0 + ty*4 + i;
        #pragma unroll
        for (int j=0;j<4;j++){
            int h = n0 + tx*4 + j;
            float v = (h<H) ? acc[i][j] + blin[h] : 0.f;
            g_gs[m][h] = v;
            g_hin[m][h] = v;
        }
    }
}

// ---------------- fused: [gemm1(idx) | vert(idx)+edge(idx-1)] -----------------
// all parts read the SAME g_gs snapshot; gemm writes g_hin, vert/edge write out + caches
__global__ __launch_bounds__(256) void kfused1(
    const float* __restrict__ dep, const float* __restrict__ bgate,
    const float* __restrict__ bmap, const float* __restrict__ Wv,
    const float* __restrict__ bv, const float* __restrict__ We,
    const float* __restrict__ be, float* __restrict__ out, int idx)
{
    __shared__ float As[2][16][68];
    __shared__ float Bs[2][16][64];
    int gemmBlocks = (idx >= 1) ? 128 : 0;
    int bid = blockIdx.x;
    int t = threadIdx.x;

    if (bid < gemmBlocks){
        // ---- GEMM1: GM = gs @ WcatT, epilogue -> g_hin ----
        int nt = bid & 15, mt = bid >> 4;
        int m0 = mt*64, n0 = nt*64;
        float acc[4][4];
        #pragma unroll
        for (int i=0;i<4;i++)
            #pragma unroll
            for (int j=0;j<4;j++) acc[i][j] = 0.f;
        gemm_db_64x64(&g_gs[0][0], &g_WcatT[0][0], 1024, m0, n0, acc, As, Bs);
        int tx = t & 15, ty = t >> 4;
        int hbase = (n0>>1) + tx*2;
        #pragma unroll
        for (int i=0;i<4;i++){
            int m = m0 + ty*4 + i;
            float rb = dep[m*(S*S) + idx*S + (idx-1)];
            #pragma unroll
            for (int p=0;p<2;p++){
                int h = hbase + p;
                float val = 0.f;
                if (h < H){
                    float f0 = g_f0[h];
                    float fv = (rb != 0.f)
                        ? sigm(acc[i][2*p] + bgate[h]) * (acc[i][2*p+1] + bmap[h])
                        : f0;
                    val = 15.f*f0 + fv;
                }
                g_hin[m][h] = val;
            }
        }
        return;
    }

    // ---- merged vertex + edge block, b = bid - gemmBlocks ----
    float* red = &As[0][0][0];
    int b = bid - gemmBlocks;
    int w = t >> 5, lane = t & 31;

    if (w < C){
        // vertex logit for class w
        float s = 0.f;
        for (int k = lane; k < H; k += 32) s += g_gs[b][k] * Wv[w*H + k];
        #pragma unroll
        for (int o=16;o>0;o>>=1) s += __shfl_down_sync(0xffffffffu, s, o);
        if (lane == 0) red[w] = s + bv[w];
    } else if (idx >= 1){
        // warp 7: both edge dots, no barrier needed — lane 0 finishes the row
        float s1 = 0.f, s2 = 0.f;
        for (int k = lane; k < H; k += 32){
            float g = g_gs[b][k];
            s1 += g * We[k];
            s2 += g * We[H + k];
        }
        #pragma unroll
        for (int o=16;o>0;o>>=1){
            s1 += __shfl_down_sync(0xffffffffu, s1, o);
            s2 += __shfl_down_sync(0xffffffffu, s2, o);
        }
        if (lane == 0){
            int eidx = idx - 1;
            float bev = be[0];
            float a_old = g_aprev[b];
            float* row = out + DEP_OFF + (b*S + eidx)*S;
            #pragma unroll
            for (int col=0; col<S; col++){
                float v;
                if (col >= eidx) v = 0.f;
                else if (col == eidx-1) v = (a_old + g_d[b][eidx-1] + bev >= 0.f) ? 1.f : 0.f;
                else v = (s1 + g_d[b][col] + bev >= 0.f) ? 1.f : 0.f;
                row[col] = v;
            }
            g_d[b][eidx] = s2;
            g_aprev[b] = s1;
        }
    }
    __syncthreads();
    if (t == 0){
        float mx = red[0];
        #pragma unroll
        for (int c=1;c<C;c++) mx = fmaxf(mx, red[c]);
        float e[C]; float sum = 0.f;
        #pragma unroll
        for (int c=0;c<C;c++){ e[c] = expf(red[c]-mx); sum += e[c]; }
        float inv = 1.f/sum;
        float* o = out + ENC_OFF + (b*S + idx)*C;
        #pragma unroll
        for (int c=0;c<C;c++) o[c] = e[c]*inv;
    }
}

// ---------------- K2: gh = h_in @ Whh3T, GRU epilogue -> g_gs ----------------
// grid 256 (32 ntiles x 8 mtiles), 256 thr, BM=64 BN=48 BK=16, tile 4x3, double-buffered
__global__ __launch_bounds__(256) void kgemm2(const float* __restrict__ Wih,
                                              const float* __restrict__ bih,
                                              const float* __restrict__ bhh, int idx)
{
    __shared__ float As[2][16][68];
    __shared__ float Bs[2][16][48];
    int bid = blockIdx.x;
    int nt = bid & 31, mt = bid >> 5;
    int m0 = mt*64, n0 = nt*48;
    int t = threadIdx.x, tx = t & 15, ty = t >> 4;
    int am = t & 63, akq = t >> 6;
    int kb = 0, nbc = 0;
    bool bprod = (t < 192);
    if (bprod){ kb = t/12; nbc = (t%12)*4; }
    float acc[4][3];
    #pragma unroll
    for (int i=0;i<4;i++)
        #pragma unroll
        for (int j=0;j<3;j++) acc[i][j] = 0.f;

    // prologue
    float4 av = *(const float4*)&g_hin[m0+am][akq*4];
    float4 bv = make_float4(0.f,0.f,0.f,0.f);
    if (bprod) bv = *(const float4*)&g_Whh3T[kb][n0 + nbc];
    As[0][akq*4+0][am]=av.x; As[0][akq*4+1][am]=av.y;
    As[0][akq*4+2][am]=av.z; As[0][akq*4+3][am]=av.w;
    if (bprod) *(float4*)&Bs[0][kb][nbc] = bv;
    __syncthreads();

    int buf = 0;
    for (int k0 = 16; k0 <= KP; k0 += 16){
        bool more = (k0 < KP);
        if (more){
            av = *(const float4*)&g_hin[m0+am][k0 + akq*4];
            if (bprod) bv = *(const float4*)&g_Whh3T[k0+kb][n0 + nbc];
        }
        #pragma unroll
        for (int kk = 0; kk < 16; kk++){
            float4 a4 = *(const float4*)&As[buf][kk][ty*4];
            float b0 = Bs[buf][kk][tx*3+0];
            float b1 = Bs[buf][kk][tx*3+1];
            float b2 = Bs[buf][kk][tx*3+2];
            float a[4] = {a4.x,a4.y,a4.z,a4.w};
            #pragma unroll
            for (int i=0;i<4;i++){
                acc[i][0] += a[i]*b0;
                acc[i][1] += a[i]*b1;
                acc[i][2] += a[i]*b2;
            }
        }
        if (more){
            int nb = buf ^ 1;
            As[nb][akq*4+0][am]=av.x; As[nb][akq*4+1][am]=av.y;
            As[nb][akq*4+2][am]=av.z; As[nb][akq*4+3][am]=av.w;
            if (bprod) *(float4*)&Bs[nb][kb][nbc] = bv;
            __syncthreads();
            buf = nb;
        }
    }

    int h = nt*16 + tx;
    if (h < H){
        float bh_r = bhh[h], bh_z = bhh[H+h], bh_n = bhh[2*H+h];
        float bi_r = bih[h], bi_z = bih[H+h], bi_n = bih[2*H+h];
        #pragma unroll
        for (int i=0;i<4;i++){
            int m = m0 + ty*4 + i;
            int c = g_cls[m*S + idx];
            float gh_r = acc[i][0] + bh_r;
            float gh_z = acc[i][1] + bh_z;
            float gh_n = acc[i][2] + bh_n;
            float gi_r = Wih[(      h)*C + c] + bi_r;
            float gi_z = Wih[(H   + h)*C + c] + bi_z;
            float gi_n = Wih[(2*H + h)*C + c] + bi_n;
            float rr = sigm(gi_r + gh_r);
            float u  = sigm(gi_z + gh_z);
            float nn = tanhf(gi_n + rr*gh_n);
            float hv = (1.f-u)*nn + u*g_hin[m][h];
            g_gs[m][h] = hv;
        }
    }
}

// ---------------- final edge row (idx = S-1) ----------------
__global__ __launch_bounds__(256) void kedge_final(const float* __restrict__ We,
                                                   const float* __restrict__ be,
                                                   float* __restrict__ out)
{
    __shared__ float red[8];
    int b = blockIdx.x;
    int t = threadIdx.x;
    int w = t >> 5, lane = t & 31;
    const int eidx = S - 1;
    float s1 = 0.f;
    for (int k = t; k < H; k += 256){
        s1 += g_gs[b][k] * We[k];
    }
    #pragma unroll
    for (int o=16;o>0;o>>=1) s1 += __shfl_down_sync(0xffffffffu, s1, o);
    if (lane == 0) red[w] = s1;
    __syncthreads();
    if (t == 0){
        float a_new = 0.f;
        #pragma unroll
        for (int i=0;i<8;i++) a_new += red[i];
        float bev = be[0];
        float a_old = g_aprev[b];
        float* row = out + DEP_OFF + (b*S + eidx)*S;
        #pragma unroll
        for (int col=0; col<S; col++){
            float v;
            if (col >= eidx) v = 0.f;
            else if (col == eidx-1) v = (a_old + g_d[b][eidx-1] + bev >= 0.f) ? 1.f : 0.f;
            else v = (a_new + g_d[b][col] + bev >= 0.f) ? 1.f : 0.f;
            row[col] = v;
        }
    }
}

// ---------------- launch ----------------
extern "C" void kernel_launch(void* const* d_in, const int* in_sizes, int n_in,
                              void* d_out, int out_size)
{
    const float* z     = (const float*)d_in[0];
    const float* dep   = (const float*)d_in[1];
    const float* ne    = (const float*)d_in[2];
    const float* Wlin  = (const float*)d_in[3];
    const float* blin  = (const float*)d_in[4];
    const float* Wv    = (const float*)d_in[5];
    const float* bv    = (const float*)d_in[6];
    const float* We    = (const float*)d_in[7];
    const float* be    = (const float*)d_in[8];
    const float* Wg    = (const float*)d_in[9];
    const float* bgate = (const float*)d_in[10];
    const float* Wm    = (const float*)d_in[11];
    const float* bmap  = (const float*)d_in[12];
    const float* Wih   = (const float*)d_in[13];
    const float* bih   = (const float*)d_in[14];
    const float* Whh   = (const float*)d_in[15];
    const float* bhh   = (const float*)d_in[16];
    float* out = (float*)d_out;

    kinit<<<1024, 256>>>(Wg, Wm, Whh, Wlin, bgate, bmap, z, ne);
    kgemm0<<<64, 256>>>(blin);
    for (int idx=0; idx<S; ++idx){
        int grid = (idx >= 1) ? (128 + 512) : 512;
        kfused1<<<grid, 256>>>(dep, bgate, bmap, Wv, bv, We, be, out, idx);
        kgemm2<<<256, 256>>>(Wih, bih, bhh, idx);
    }
    kedge_final<<<B, 256>>>(We, be, out);
    (void)in_sizes; (void)n_in; (void)out_size;
}

// round 12
// speedup vs baseline: 1.8341x; 1.0374x over previous
#include <cuda_runtime.h>
#include <math.h>

// Problem constants
#define B 512
#define S 16
#define H 501
#define C 7
#define KP 512          // padded K (inner dim)
#define DEP_OFF 0
#define ENC_OFF (B*S*S) // 131072

// ---------------- device state ----------------
__device__ float g_gs  [B][KP];        // graph state (padded, tail zeros)
__device__ float g_hin [B][KP];        // h_in buffer (padded, tail zeros)
__device__ float g_zpad[B][KP];        // padded z
__device__ float g_WcatT[KP][1024];    // B matrix for K1: [k][2h+e], e=0 gate, e=1 map
__device__ float g_Whh3T[KP][1536];    // B matrix for K2: [k][3h+j], j=r,z,n
__device__ float g_WlinT[KP][KP];      // W_lin1^T padded
__device__ float g_f0[KP];             // sigmoid(b_gate)*b_map
__device__ float g_ghc[1536];          // (16*f0) @ Whh3T  (constant gh for rb==0 rows)
__device__ int   g_cls[B*S];           // argmax of one-hot node encoding
__device__ float g_d[B][S];            // cached dots nhs[j]·we2
__device__ float g_aprev[B];           // cached dot hv·we1
__device__ int   g_rows[B];            // compacted rows with rb != 0 (stable order)
__device__ int   g_cnt;                // number of compacted rows

__device__ __forceinline__ float sigm(float x){ return 1.0f/(1.0f+expf(-x)); }

// ---------------- init: transpose/interleave weights, pad z, f0, classes ----------------
__global__ void kinit(const float* __restrict__ Wg, const float* __restrict__ Wm,
                      const float* __restrict__ Whh, const float* __restrict__ Wlin,
                      const float* __restrict__ bgate, const float* __restrict__ bmap,
                      const float* __restrict__ z, const float* __restrict__ ne)
{
    int gt = blockIdx.x*blockDim.x + threadIdx.x;
    int gstep = gridDim.x*blockDim.x;
    for (int i=gt; i<KP*1024; i+=gstep){
        int k = i>>10, n = i & 1023; int h = n>>1, e = n&1;
        float v = 0.f;
        if (k<H && h<H) v = e ? Wm[h*H+k] : Wg[h*H+k];
        (&g_WcatT[0][0])[i] = v;
    }
    for (int i=gt; i<KP*1536; i+=gstep){
        int k = i/1536, n = i%1536; int h = n/3, j = n%3;
        float v = 0.f;
        if (k<H && h<H) v = Whh[(j*H+h)*H + k];
        (&g_Whh3T[0][0])[i] = v;
    }
    for (int i=gt; i<KP*KP; i+=gstep){
        int k = i>>9, h = i & 511;
        float v = 0.f;
        if (k<H && h<H) v = Wlin[h*H+k];
        (&g_WlinT[0][0])[i] = v;
    }
    for (int i=gt; i<B*KP; i+=gstep){
        int b = i>>9, k = i & 511;
        (&g_zpad[0][0])[i] = (k<H) ? z[b*H+k] : 0.f;
    }
    for (int i=gt; i<KP; i+=gstep){
        g_f0[i] = (i<H) ? sigm(bgate[i])*bmap[i] : 0.f;
    }
    for (int i=gt; i<B*S; i+=gstep){
        const float* p = ne + i*C;
        int best = 0; float bv = p[0];
        #pragma unroll
        for (int c=1;c<C;c++){ if (p[c] > bv){ bv = p[c]; best = c; } }
        g_cls[i] = best;
    }
}

// ---------------- prep: ghc = (16*f0) @ Whh3T ----------------
__global__ void kprep()
{
    int n = blockIdx.x*blockDim.x + threadIdx.x;   // 0..1535
    if (n >= 1536) return;
    float s = 0.f;
    for (int k = 0; k < KP; k++) s += 16.f*g_f0[k] * g_Whh3T[k][n];
    g_ghc[n] = s;
}

// ---------------- per-idx row compaction (deterministic, stable order) ----------------
__global__ void kcompact(const float* __restrict__ dep, int idx)
{
    __shared__ int wsum[16];    // per-warp flag counts
    int t = threadIdx.x;        // 512 threads, 16 warps
    int w = t >> 5, lane = t & 31;
    if (idx == 0){
        g_rows[t] = t;
        if (t == 0) g_cnt = B;
        return;
    }
    float rb = dep[t*(S*S) + idx*S + (idx-1)];
    int flag = (rb != 0.f) ? 1 : 0;
    unsigned mask = __ballot_sync(0xffffffffu, flag);
    int wprefix = __popc(mask & ((1u << lane) - 1u));
    if (lane == 0) wsum[w] = __popc(mask);
    __syncthreads();
    // thread 0 scans warp totals (16 entries) into exclusive offsets
    __shared__ int woff[16];
    __shared__ int total;
    if (t == 0){
        int run = 0;
        #pragma unroll
        for (int i=0;i<16;i++){ woff[i] = run; run += wsum[i]; }
        total = run;
        g_cnt = run;
    }
    __syncthreads();
    if (flag) g_rows[woff[w] + wprefix] = t;
    // pad the tail deterministically
    int c = total;
    for (int i = c + t; i < B; i += 512) g_rows[i] = 0;
}

// ---------------- gathered 64x64 GEMM core: BM=64, BN=64, BK=16, 256 thr, tile 4x4 ----
// A rows taken from srows[0..63] (indices into A's row dim)
__device__ __forceinline__ void gemm_core_g(
    const float* __restrict__ A,      // [..][KP]
    const float* __restrict__ Bm,     // [KP][NB]
    int NB, int n0, const int* srows,
    float acc[4][4], float As[16][68], float Bs[16][64])
{
    int t = threadIdx.x;
    int tx = t & 15, ty = t >> 4;
    int am = t & 63, akq = t >> 6;      // A producer: local row, 4-float chunk
    int bk = t >> 4, bn = (t & 15)*4;   // B producer
    int arow = srows[am];

    for (int k0 = 0; k0 < KP; k0 += 16){
        float4 av = *(const float4*)&A[(size_t)arow*KP + k0 + akq*4];
        float4 bv = *(const float4*)&Bm[(size_t)(k0+bk)*NB + n0 + bn];
        As[akq*4+0][am]=av.x; As[akq*4+1][am]=av.y;
        As[akq*4+2][am]=av.z; As[akq*4+3][am]=av.w;
        *(float4*)&Bs[bk][bn] = bv;
        __syncthreads();
        #pragma unroll
        for (int kk = 0; kk < 16; kk++){
            float4 a4 = *(const float4*)&As[kk][ty*4];
            float4 b4 = *(const float4*)&Bs[kk][tx*4];
            float a[4] = {a4.x,a4.y,a4.z,a4.w};
            float bb[4] = {b4.x,b4.y,b4.z,b4.w};
            #pragma unroll
            for (int i=0;i<4;i++)
                #pragma unroll
                for (int j=0;j<4;j++) acc[i][j] += a[i]*bb[j];
        }
        __syncthreads();
    }
}

// ---------------- GEMM gs0 = zpad @ WlinT + b_lin1 ; writes g_gs and g_hin ----------------
// grid 64 (8 ntiles x 8 mtiles), 256 thr — identity rows
__global__ __launch_bounds__(256) void kgemm0(const float* __restrict__ blin)
{
    __shared__ float As[16][68];
    __shared__ float Bs[16][64];
    __shared__ int srows[64];
    int nt = blockIdx.x & 7, mt = blockIdx.x >> 3;
    int m0 = mt*64, n0 = nt*64;
    int t = threadIdx.x;
    if (t < 64) srows[t] = m0 + t;
    __syncthreads();
    float acc[4][4];
    #pragma unroll
    for (int i=0;i<4;i++)
        #pragma unroll
        for (int j=0;j<4;j++) acc[i][j] = 0.f;
    gemm_core_g(&g_zpad[0][0], &g_WlinT[0][0], KP, n0, srows, acc, As, Bs);
    int tx = t & 15, ty = t >> 4;
    #pragma unroll
    for (int i=0;i<4;i++){
        int m = m0 + ty*4 + i;
        #pragma unroll
        for (int j=0;j<4;j++){
            int h = n0 + tx*4 + j;
            float v = (h<H) ? acc[i][j] + blin[h] : 0.f;
            g_gs[m][h] = v;
            g_hin[m][h] = v;
        }
    }
}

// ---------------- fused: [gemm1(idx) gathered | vert(idx)+edge(idx-1)] -----------------
__global__ __launch_bounds__(256) void kfused1(
    const float* __restrict__ dep, const float* __restrict__ bgate,
    const float* __restrict__ bmap, const float* __restrict__ Wv,
    const float* __restrict__ bv, const float* __restrict__ We,
    const float* __restrict__ be, float* __restrict__ out, int idx)
{
    __shared__ float As[16][68];
    __shared__ float Bs[16][64];
    __shared__ int srows[64];
    int gemmBlocks = (idx >= 1) ? 128 : 0;
    int bid = blockIdx.x;
    int t = threadIdx.x;

    if (bid < gemmBlocks){
        // ---- GEMM1 on compacted rows: GM = gs @ WcatT, epilogue -> g_hin ----
        int nt = bid & 15, mt = bid >> 4;
        int m0 = mt*64, n0 = nt*64;
        int cnt = g_cnt;
        if (m0 >= cnt) return;
        if (t < 64) srows[t] = g_rows[m0 + t];
        __syncthreads();
        float acc[4][4];
        #pragma unroll
        for (int i=0;i<4;i++)
            #pragma unroll
            for (int j=0;j<4;j++) acc[i][j] = 0.f;
        gemm_core_g(&g_gs[0][0], &g_WcatT[0][0], 1024, n0, srows, acc, As, Bs);
        int tx = t & 15, ty = t >> 4;
        int hbase = (n0>>1) + tx*2;
        #pragma unroll
        for (int i=0;i<4;i++){
            int ml = ty*4 + i;
            if (m0 + ml >= cnt) continue;
            int m = srows[ml];
            #pragma unroll
            for (int p=0;p<2;p++){
                int h = hbase + p;
                float val = 0.f;
                if (h < H){
                    float f0 = g_f0[h];
                    float fv = sigm(acc[i][2*p] + bgate[h]) * (acc[i][2*p+1] + bmap[h]);
                    val = 15.f*f0 + fv;
                }
                g_hin[m][h] = val;
            }
        }
        return;
    }

    // ---- merged vertex + edge block, b = bid - gemmBlocks ----
    float* red = &As[0][0];
    int b = bid - gemmBlocks;
    int w = t >> 5, lane = t & 31;

    if (w < C){
        float s = 0.f;
        for (int k = lane; k < H; k += 32) s += g_gs[b][k] * Wv[w*H + k];
        #pragma unroll
        for (int o=16;o>0;o>>=1) s += __shfl_down_sync(0xffffffffu, s, o);
        if (lane == 0) red[w] = s + bv[w];
    } else if (idx >= 1){
        float s1 = 0.f, s2 = 0.f;
        for (int k = lane; k < H; k += 32){
            float g = g_gs[b][k];
            s1 += g * We[k];
            s2 += g * We[H + k];
        }
        #pragma unroll
        for (int o=16;o>0;o>>=1){
            s1 += __shfl_down_sync(0xffffffffu, s1, o);
            s2 += __shfl_down_sync(0xffffffffu, s2, o);
        }
        if (lane == 0){
            int eidx = idx - 1;
            float bev = be[0];
            float a_old = g_aprev[b];
            float* row = out + DEP_OFF + (b*S + eidx)*S;
            #pragma unroll
            for (int col=0; col<S; col++){
                float v;
                if (col >= eidx) v = 0.f;
                else if (col == eidx-1) v = (a_old + g_d[b][eidx-1] + bev >= 0.f) ? 1.f : 0.f;
                else v = (s1 + g_d[b][col] + bev >= 0.f) ? 1.f : 0.f;
                row[col] = v;
            }
            g_d[b][eidx] = s2;
            g_aprev[b] = s1;
        }
    }
    __syncthreads();
    if (t == 0){
        float mx = red[0];
        #pragma unroll
        for (int c=1;c<C;c++) mx = fmaxf(mx, red[c]);
        float e[C]; float sum = 0.f;
        #pragma unroll
        for (int c=0;c<C;c++){ e[c] = expf(red[c]-mx); sum += e[c]; }
        float inv = 1.f/sum;
        float* o = out + ENC_OFF + (b*S + idx)*C;
        #pragma unroll
        for (int c=0;c<C;c++) o[c] = e[c]*inv;
    }
}

// ---------------- K2 gathered: gh = h_in @ Whh3T + GRU -> g_gs, plus rb==0 GRU blocks ----
// grid 256 GEMM blocks (32 nt x 8 mt) + 64 elementwise blocks, 256 thr
__global__ __launch_bounds__(256) void kgemm2c(const float* __restrict__ dep,
                                               const float* __restrict__ Wih,
                                               const float* __restrict__ bih,
                                               const float* __restrict__ bhh, int idx)
{
    __shared__ float As[16][68];
    __shared__ float Bs[16][48];
    __shared__ int srows[64];
    int bid = blockIdx.x;
    int t = threadIdx.x;

    if (bid >= 256){
        // ---- elementwise GRU for rb==0 rows (only idx >= 1) ----
        if (idx == 0) return;
        int r0 = (bid - 256) * 8;
        for (int rr = 0; rr < 8; rr++){
            int m = r0 + rr;
            float rb = dep[m*(S*S) + idx*S + (idx-1)];
            if (rb != 0.f) continue;
            int c = g_cls[m*S + idx];
            for (int h = t; h < H; h += 256){
                float hin = 16.f * g_f0[h];
                float gh_r = g_ghc[h*3+0] + bhh[h];
                float gh_z = g_ghc[h*3+1] + bhh[H+h];
                float gh_n = g_ghc[h*3+2] + bhh[2*H+h];
                float gi_r = Wih[(      h)*C + c] + bih[h];
                float gi_z = Wih[(H   + h)*C + c] + bih[H+h];
                float gi_n = Wih[(2*H + h)*C + c] + bih[2*H+h];
                float rg = sigm(gi_r + gh_r);
                float u  = sigm(gi_z + gh_z);
                float nn = tanhf(gi_n + rg*gh_n);
                g_gs[m][h] = (1.f-u)*nn + u*hin;
            }
        }
        return;
    }

    int nt = bid & 31, mt = bid >> 5;
    int m0 = mt*64, n0 = nt*48;
    int cnt = g_cnt;
    if (m0 >= cnt) return;
    if (t < 64) srows[t] = g_rows[m0 + t];
    __syncthreads();

    int tx = t & 15, ty = t >> 4;
    int am = t & 63, akq = t >> 6;
    int arow = srows[am];
    float acc[4][3];
    #pragma unroll
    for (int i=0;i<4;i++)
        #pragma unroll
        for (int j=0;j<3;j++) acc[i][j] = 0.f;

    for (int k0 = 0; k0 < KP; k0 += 16){
        float4 av = *(const float4*)&g_hin[arow][k0 + akq*4];
        As[akq*4+0][am]=av.x; As[akq*4+1][am]=av.y;
        As[akq*4+2][am]=av.z; As[akq*4+3][am]=av.w;
        if (t < 192){
            int kb = t/12, nbc = (t%12)*4;
            *(float4*)&Bs[kb][nbc] = *(const float4*)&g_Whh3T[k0+kb][n0 + nbc];
        }
        __syncthreads();
        #pragma unroll
        for (int kk = 0; kk < 16; kk++){
            float4 a4 = *(const float4*)&As[kk][ty*4];
            float b0 = Bs[kk][tx*3+0];
            float b1 = Bs[kk][tx*3+1];
            float b2 = Bs[kk][tx*3+2];
            float a[4] = {a4.x,a4.y,a4.z,a4.w};
            #pragma unroll
            for (int i=0;i<4;i++){
                acc[i][0] += a[i]*b0;
                acc[i][1] += a[i]*b1;
                acc[i][2] += a[i]*b2;
            }
        }
        __syncthreads();
    }

    int h = nt*16 + tx;
    if (h < H){
        float bh_r = bhh[h], bh_z = bhh[H+h], bh_n = bhh[2*H+h];
        float bi_r = bih[h], bi_z = bih[H+h], bi_n = bih[2*H+h];
        #pragma unroll
        for (int i=0;i<4;i++){
            int ml = ty*4 + i;
            if (m0 + ml >= cnt) continue;
            int m = srows[ml];
            int c = g_cls[m*S + idx];
            float gh_r = acc[i][0] + bh_r;
            float gh_z = acc[i][1] + bh_z;
            float gh_n = acc[i][2] + bh_n;
            float gi_r = Wih[(      h)*C + c] + bi_r;
            float gi_z = Wih[(H   + h)*C + c] + bi_z;
            float gi_n = Wih[(2*H + h)*C + c] + bi_n;
            float rr = sigm(gi_r + gh_r);
            float u  = sigm(gi_z + gh_z);
            float nn = tanhf(gi_n + rr*gh_n);
            float hv = (1.f-u)*nn + u*g_hin[m][h];
            g_gs[m][h] = hv;
        }
    }
}

// ---------------- final edge row (idx = S-1) ----------------
__global__ __launch_bounds__(256) void kedge_final(const float* __restrict__ We,
                                                   const float* __restrict__ be,
                                                   float* __restrict__ out)
{
    __shared__ float red[8];
    int b = blockIdx.x;
    int t = threadIdx.x;
    int w = t >> 5, lane = t & 31;
    const int eidx = S - 1;
    float s1 = 0.f;
    for (int k = t; k < H; k += 256){
        s1 += g_gs[b][k] * We[k];
    }
    #pragma unroll
    for (int o=16;o>0;o>>=1) s1 += __shfl_down_sync(0xffffffffu, s1, o);
    if (lane == 0) red[w] = s1;
    __syncthreads();
    if (t == 0){
        float a_new = 0.f;
        #pragma unroll
        for (int i=0;i<8;i++) a_new += red[i];
        float bev = be[0];
        float a_old = g_aprev[b];
        float* row = out + DEP_OFF + (b*S + eidx)*S;
        #pragma unroll
        for (int col=0; col<S; col++){
            float v;
            if (col >= eidx) v = 0.f;
            else if (col == eidx-1) v = (a_old + g_d[b][eidx-1] + bev >= 0.f) ? 1.f : 0.f;
            else v = (a_new + g_d[b][col] + bev >= 0.f) ? 1.f : 0.f;
            row[col] = v;
        }
    }
}

// ---------------- launch ----------------
extern "C" void kernel_launch(void* const* d_in, const int* in_sizes, int n_in,
                              void* d_out, int out_size)
{
    const float* z     = (const float*)d_in[0];
    const float* dep   = (const float*)d_in[1];
    const float* ne    = (const float*)d_in[2];
    const float* Wlin  = (const float*)d_in[3];
    const float* blin  = (const float*)d_in[4];
    const float* Wv    = (const float*)d_in[5];
    const float* bv    = (const float*)d_in[6];
    const float* We    = (const float*)d_in[7];
    const float* be    = (const float*)d_in[8];
    const float* Wg    = (const float*)d_in[9];
    const float* bgate = (const float*)d_in[10];
    const float* Wm    = (const float*)d_in[11];
    const float* bmap  = (const float*)d_in[12];
    const float* Wih   = (const float*)d_in[13];
    const float* bih   = (const float*)d_in[14];
    const float* Whh   = (const float*)d_in[15];
    const float* bhh   = (const float*)d_in[16];
    float* out = (float*)d_out;

    kinit<<<1024, 256>>>(Wg, Wm, Whh, Wlin, bgate, bmap, z, ne);
    kprep<<<6, 256>>>();
    kgemm0<<<64, 256>>>(blin);
    for (int idx=0; idx<S; ++idx){
        kcompact<<<1, 512>>>(dep, idx);
        int grid = (idx >= 1) ? (128 + 512) : 512;
        kfused1<<<grid, 256>>>(dep, bgate, bmap, Wv, bv, We, be, out, idx);
        kgemm2c<<<320, 256>>>(dep, Wih, bih, bhh, idx);
    }
    kedge_final<<<B, 256>>>(We, be, out);
    (void)in_sizes; (void)n_in; (void)out_size;
}